// round 10
// baseline (speedup 1.0000x reference)
#include <cuda_runtime.h>
#include <math.h>

#define VOCAB 32000
#define Q4    8000     // float4 per row
#define KNN   32
#define NT    512
#define NC    296      // persistent CTAs: 2 per SM
#define LOG2E 1.4426950408889634f

__device__ __forceinline__ float warp_max(float v) {
    #pragma unroll
    for (int o = 16; o > 0; o >>= 1) v = fmaxf(v, __shfl_xor_sync(0xFFFFFFFFu, v, o));
    return v;
}
__device__ __forceinline__ float warp_sum(float v) {
    #pragma unroll
    for (int o = 16; o > 0; o >>= 1) v += __shfl_xor_sync(0xFFFFFFFFu, v, o);
    return v;
}

__device__ __forceinline__ float4 ldlu4(const float4* p) {
    float4 r;
    asm volatile("ld.global.lu.v4.f32 {%0,%1,%2,%3}, [%4];"
                 : "=f"(r.x), "=f"(r.y), "=f"(r.z), "=f"(r.w) : "l"(p));
    return r;
}
__device__ __forceinline__ void stcs4(float4* p, float4 v) {
    asm volatile("st.global.cs.v4.f32 [%0], {%1,%2,%3,%4};"
                 :: "l"(p), "f"(v.x), "f"(v.y), "f"(v.z), "f"(v.w) : "memory");
}

__global__ __launch_bounds__(NT, 2)
void knn_model_kernel(const float* __restrict__ logits,
                      const int*   __restrict__ optor_vals,
                      const float* __restrict__ optor_dists,
                      const int*   __restrict__ const_vals,
                      const float* __restrict__ const_dists,
                      const int*   __restrict__ prev_words,
                      const float* __restrict__ optor_lamda,
                      const float* __restrict__ const_lamda,
                      const float* __restrict__ optor_temp,
                      const float* __restrict__ const_temp,
                      float*       __restrict__ out,
                      int          rows)
{
    __shared__ float red[16];
    __shared__ float lscale_sh;

    const int c    = blockIdx.x;              // persistent CTA id
    const int tid  = threadIdx.x;
    const int wid  = tid >> 5;
    const int lane = tid & 31;

    const float ol = optor_lamda[0];
    const float cl = const_lamda[0];
    const float otp = optor_temp[0];
    const float ctp = const_temp[0];

    // ---- prologue: read first row (DRAM -> L2), partial exp-sum ----
    float s = 0.0f;
    {
        const float4* l4 = (const float4*)(logits + (size_t)c * VOCAB);
        #pragma unroll 4
        for (int i = tid; i < Q4; i += NT) {
            float4 x = l4[i];
            s += exp2f(x.x * LOG2E) + exp2f(x.y * LOG2E)
               + exp2f(x.z * LOG2E) + exp2f(x.w * LOG2E);
        }
    }

    for (int t = c; t < rows; t += NC) {
        // ---- block-reduce sum, compute log2-scale for row t ----
        float v = warp_sum(s);
        if (lane == 0) red[wid] = v;
        __syncthreads();
        if (tid < 32) {
            float w = (lane < 16) ? red[lane] : 0.0f;
            w = warp_sum(w);
            if (lane == 0) {
                const int p = prev_words[t];
                const bool om = (p <= 88) | ((p >= 91) & (p <= 291));
                const bool cm = (p == 89) | (p == 90) | (p >= 292);
                const float base = (om ? (1.0f - ol) : 0.0f) + (cm ? (1.0f - cl) : 0.0f);
                lscale_sh = log2f(base / w);   // scale > 0 (masks exhaustive)
            }
        }
        __syncthreads();
        const float lscale = lscale_sh;

        const float4* l4 = (const float4*)(logits + (size_t)t * VOCAB);
        float4* o4 = (float4*)(out + (size_t)t * VOCAB);
        const int tn = t + NC;
        float ns = 0.0f;

        if (tn < rows) {
            // ---- fused steady state: write row t (L2 reload) + read row t+NC (DRAM) ----
            const float4* n4 = (const float4*)(logits + (size_t)tn * VOCAB);
            #pragma unroll 2
            for (int i = tid; i < Q4; i += NT) {
                float4 xx = n4[i];             // DRAM read of next row (issues early)
                float4 x  = ldlu4(&l4[i]);     // L2 hit, last-use
                float4 y;
                y.x = exp2f(fmaf(x.x, LOG2E, lscale));
                y.y = exp2f(fmaf(x.y, LOG2E, lscale));
                y.z = exp2f(fmaf(x.z, LOG2E, lscale));
                y.w = exp2f(fmaf(x.w, LOG2E, lscale));
                stcs4(&o4[i], y);              // DRAM write of current row
                ns += exp2f(xx.x * LOG2E) + exp2f(xx.y * LOG2E)
                    + exp2f(xx.z * LOG2E) + exp2f(xx.w * LOG2E);
            }
        } else {
            // ---- epilogue: last row, write only ----
            #pragma unroll 4
            for (int i = tid; i < Q4; i += NT) {
                float4 x = ldlu4(&l4[i]);
                float4 y;
                y.x = exp2f(fmaf(x.x, LOG2E, lscale));
                y.y = exp2f(fmaf(x.y, LOG2E, lscale));
                y.z = exp2f(fmaf(x.z, LOG2E, lscale));
                y.w = exp2f(fmaf(x.w, LOG2E, lscale));
                stcs4(&o4[i], y);
            }
        }
        __syncthreads();   // row t base stores issued before scatter atomics

        // ---- scatter for row t (warp 0: optor, warp 1: const) ----
        float* orow = out + (size_t)t * VOCAB;
        if (wid == 0) {
            const int p = prev_words[t];
            const bool om = (p <= 88) | ((p >= 91) & (p <= 291));
            const float d = optor_dists[(size_t)t * KNN + lane];
            const float x = -d / otp;
            const float mm = warp_max(x);
            const float e  = __expf(x - mm);
            const float ss = warp_sum(e);
            if (om) atomicAdd(&orow[optor_vals[(size_t)t * KNN + lane]], ol * e / ss);
        } else if (wid == 1) {
            const int p = prev_words[t];
            const bool cm = (p == 89) | (p == 90) | (p >= 292);
            const float d = const_dists[(size_t)t * KNN + lane];
            const float x = -d / ctp;
            const float mm = warp_max(x);
            const float e  = __expf(x - mm);
            const float ss = warp_sum(e);
            if (cm) atomicAdd(&orow[const_vals[(size_t)t * KNN + lane]], cl * e / ss);
        }

        s = ns;
    }
}

extern "C" void kernel_launch(void* const* d_in, const int* in_sizes, int n_in,
                              void* d_out, int out_size)
{
    const float* logits      = (const float*)d_in[0];
    const int*   optor_vals  = (const int*)  d_in[1];
    const float* optor_dists = (const float*)d_in[2];
    const int*   const_vals  = (const int*)  d_in[3];
    const float* const_dists = (const float*)d_in[4];
    const int*   prev_words  = (const int*)  d_in[5];
    const float* optor_lamda = (const float*)d_in[6];
    const float* const_lamda = (const float*)d_in[7];
    const float* optor_temp  = (const float*)d_in[8];
    const float* const_temp  = (const float*)d_in[9];
    float* out = (float*)d_out;

    const int rows = in_sizes[5];                 // B*S = 1024

    knn_model_kernel<<<NC, NT>>>(
        logits, optor_vals, optor_dists, const_vals, const_dists,
        prev_words, optor_lamda, const_lamda, optor_temp, const_temp, out, rows);
}